// round 15
// baseline (speedup 1.0000x reference)
#include <cuda_runtime.h>
#include <cuda_fp16.h>
#include <cstdint>
#include <cstddef>

// DecorrelationGradient: out = 0.5 * (X^T X)/N - 0.5   (KAPPA = 0.5 algebraic collapse)
// X: [16384, 768] fp32.  out: [768, 768] fp32.
//
// R15: fp16 accumulators. R12/R14 showed duration invariant under occupancy
// changes at tensor=39% -> mma.sync with fp32 accum runs at half rate and we
// sit on that ceiling. f16.f16.f16.f16 MMA doubles MAC/slot. Inputs convert to
// fp16 (10-bit mantissa > bf16's 7). Split-K=16 fp32 RED combine bounds the
// fp16 chain length to 1024 terms (diag error ~6e-5, under the 1e-3 gate).
// CTA 96x96, 6 warps (2m x 3n), warp tile 48x32, launch_bounds(192,4).

#define D        768
#define NROW     16384
#define BT       96
#define NT       8
#define NTILES   36                     // NT*(NT+1)/2
#define NSPLIT   16
#define KCH      32                     // k samples per pipeline chunk
#define KSB      208                    // smem row stride: 96 m * 2B + 16B pad
#define TILE_B   (KCH * KSB)            // 6656
#define STAGE_B  (2 * TILE_B)           // 13312
#define NSTAGE   3
#define DYN_SMEM (NSTAGE * STAGE_B)     // 39936
#define OUT4     (D * D / 4)            // 147456 float4 in out

__device__ __align__(16) __half g_xh[(size_t)NROW * D];   // 24 MB fp16 copy of X

__device__ __forceinline__ uint32_t saddr(const void* p) {
    return (uint32_t)__cvta_generic_to_shared(p);
}
__device__ __forceinline__ void cp16(uint32_t s, const void* g) {
    asm volatile("cp.async.cg.shared.global [%0], [%1], 16;" :: "r"(s), "l"(g));
}
__device__ __forceinline__ void red2(float* p, float a, float b) {
    asm volatile("red.global.add.v2.f32 [%0], {%1, %2};" :: "l"(p), "f"(a), "f"(b) : "memory");
}
__device__ __forceinline__ void red1(float* p, float a) {
    asm volatile("red.global.add.f32 [%0], %1;" :: "l"(p), "f"(a) : "memory");
}

#define LDMX4T(R, A) \
    asm volatile("ldmatrix.sync.aligned.m8n8.x4.trans.shared.b16 {%0,%1,%2,%3}, [%4];" \
        : "=r"((R)[0]), "=r"((R)[1]), "=r"((R)[2]), "=r"((R)[3]) : "r"(A))

// f16 accumulate: D/C are 2 regs of half2; same (row,col) map as f32 variant,
// packed (c0,c1) and (c2,c3).
#define MMA16816H(C, A, B0, B1) \
    asm volatile("mma.sync.aligned.m16n8k16.row.col.f16.f16.f16.f16 " \
        "{%0,%1}, {%2,%3,%4,%5}, {%6,%7}, {%0,%1};" \
        : "+r"((C)[0]), "+r"((C)[1]) \
        : "r"((A)[0]), "r"((A)[1]), "r"((A)[2]), "r"((A)[3]), "r"(B0), "r"(B1))

// ---------------------------------------------------------------------------
// 1) Streaming convert + out init.  x is dead after this -> __ldcs.
// ---------------------------------------------------------------------------
__global__ void __launch_bounds__(256)
cvt_kernel(const float* __restrict__ x, float4* __restrict__ out4) {
    int t = blockIdx.x * 256 + threadIdx.x;
    if (t < OUT4)
        out4[t] = make_float4(-0.5f, -0.5f, -0.5f, -0.5f);

    size_t i = (size_t)t * 16;
    float4 v[4];
#pragma unroll
    for (int j = 0; j < 4; j++) v[j] = __ldcs((const float4*)(x + i + 4 * j));
#pragma unroll
    for (int j = 0; j < 4; j += 2) {
        union { __half2 h2[4]; uint4 u; } p;
        p.h2[0] = __floats2half2_rn(v[j].x, v[j].y);
        p.h2[1] = __floats2half2_rn(v[j].z, v[j].w);
        p.h2[2] = __floats2half2_rn(v[j + 1].x, v[j + 1].y);
        p.h2[3] = __floats2half2_rn(v[j + 1].z, v[j + 1].w);
        *(uint4*)(g_xh + i + 4 * j) = p.u;
    }
}

// ---------------------------------------------------------------------------
// 2) fp16 SYRK: 96x96 tiles, 6 warps (2m x 3n), 48x32 per warp.
//    smem tile layout: [k][m], 32 k-rows of 96 fp16 (192B data + 16B pad).
//    One tile = 32 rows x 12 chunks = 384 16B chunks; 192 threads -> 2 iters.
// ---------------------------------------------------------------------------
__device__ __forceinline__ void load_chunk(uint32_t sA, int k0,
                                           int colA, int colB,
                                           bool diag, int tid) {
#pragma unroll
    for (int i = 0; i < 2; i++) {
        int idx = tid + i * 192;        // 0..383
        int k   = idx / 12;             // 0..31
        int ch  = idx % 12;             // 16B chunk in the 192B row
        uint32_t dst = (uint32_t)k * KSB + (uint32_t)ch * 16;
        const __half* g = g_xh + (size_t)(k0 + k) * D + ch * 8;
        cp16(sA + dst, g + colA);
        if (!diag) cp16(sA + TILE_B + dst, g + colB);
    }
    asm volatile("cp.async.commit_group;" ::: "memory");
}

extern __shared__ char dyn_smem[];

__global__ void __launch_bounds__(192, 4)
gram_f16(float* __restrict__ out, int nchunks_total, float hscale) {
    int bx = blockIdx.x;
    int tile = bx % NTILES, split = bx / NTILES;
    int I = 0, t = tile;
    while (t >= NT - I) { t -= NT - I; I++; }
    int J = I + t;
    bool diag = (I == J);
    int colA = I * BT, colB = J * BT;

    int c0 = split * nchunks_total / NSPLIT;
    int c1 = (split + 1) * nchunks_total / NSPLIT;
    int nch = c1 - c0;

    int tid = threadIdx.x, lane = tid & 31, warp = tid >> 5;
    int wm = warp & 1, wn = warp >> 1;       // 2m x 3n
    int r = lane & 7, sel = lane >> 3;
    uint32_t sbase = saddr(dyn_smem);

    // ldmatrix.x4.trans per-lane offsets (within a tile buffer)
    uint32_t aoff = (uint32_t)((sel >> 1) * 8 + r) * KSB +
                    (uint32_t)(wm * 48 + (sel & 1) * 8) * 2;
    uint32_t boff = (uint32_t)((sel & 1) * 8 + r) * KSB +
                    (uint32_t)(wn * 32 + (sel >> 1) * 8) * 2;

    uint32_t c[3][4][2];                     // half2-packed fp16 accumulators
#pragma unroll
    for (int mi = 0; mi < 3; mi++)
#pragma unroll
        for (int ni = 0; ni < 4; ni++) {
            c[mi][ni][0] = 0u;
            c[mi][ni][1] = 0u;
        }

    // prologue: 2 chunks in flight
    load_chunk(sbase,           (c0 + 0) * KCH, colA, colB, diag, tid);
    load_chunk(sbase + STAGE_B, (c0 + 1) * KCH, colA, colB, diag, tid);

    for (int ch = 0; ch < nch; ch++) {
        if (ch < nch - 1) asm volatile("cp.async.wait_group 1;" ::: "memory");
        else              asm volatile("cp.async.wait_group 0;" ::: "memory");
        __syncthreads();
        // prefetch 2 ahead into slot (ch+2)%3 (chunk ch-1 fully consumed)
        int nxt = ch + 2;
        if (nxt < nch)
            load_chunk(sbase + (nxt % NSTAGE) * STAGE_B, (c0 + nxt) * KCH,
                       colA, colB, diag, tid);

        uint32_t sA = sbase + (ch % NSTAGE) * STAGE_B;
        uint32_t sB = diag ? sA : sA + TILE_B;

#pragma unroll
        for (int step = 0; step < KCH / 16; step++) {
            uint32_t kb = (uint32_t)step * (16 * KSB);
            uint32_t a[3][4];
#pragma unroll
            for (int mi = 0; mi < 3; mi++)
                LDMX4T(a[mi], sA + kb + aoff + mi * 32);        // +16 m = +32B
            uint32_t b[2][4];
#pragma unroll
            for (int p = 0; p < 2; p++)
                LDMX4T(b[p], sB + kb + boff + p * 32);          // +16 n = +32B
#pragma unroll
            for (int mi = 0; mi < 3; mi++)
#pragma unroll
                for (int ni = 0; ni < 4; ni++) {
                    uint32_t* bp = b[ni >> 1];
                    if (ni & 1) MMA16816H(c[mi][ni], a[mi], bp[2], bp[3]);
                    else        MMA16816H(c[mi][ni], a[mi], bp[0], bp[1]);
                }
        }
    }

    // epilogue: unpack fp16 accum -> fp32, scale, RED into out (direct + mirror)
    int mw = I * BT + wm * 48 + (lane >> 2);
    int nw = J * BT + wn * 32 + 2 * (lane & 3);

#pragma unroll
    for (int mi = 0; mi < 3; mi++) {
        int m = mw + mi * 16;
#pragma unroll
        for (int ni = 0; ni < 4; ni++) {
            int n = nw + ni * 8;
            float2 f01 = __half22float2(*(__half2*)&c[mi][ni][0]);
            float2 f23 = __half22float2(*(__half2*)&c[mi][ni][1]);
            float v0 = hscale * f01.x, v1 = hscale * f01.y;
            float v2 = hscale * f23.x, v3 = hscale * f23.y;
            red2(&out[(size_t)m * D + n],       v0, v1);
            red2(&out[(size_t)(m + 8) * D + n], v2, v3);
            if (!diag) {
                red1(&out[(size_t)n * D + m],           v0);
                red1(&out[(size_t)(n + 1) * D + m],     v1);
                red1(&out[(size_t)n * D + m + 8],       v2);
                red1(&out[(size_t)(n + 1) * D + m + 8], v3);
            }
        }
    }
}

extern "C" void kernel_launch(void* const* d_in, const int* in_sizes, int n_in,
                              void* d_out, int out_size) {
    const float* x = (const float*)d_in[0];
    float* out = (float*)d_out;
    int N = in_sizes[0] / D;            // 16384
    int nchunks = N / KCH;              // 512

    int nelem = N * D;                  // 12,582,912
    cvt_kernel<<<nelem / (256 * 16), 256>>>(x, (float4*)out);

    cudaFuncSetAttribute(gram_f16, cudaFuncAttributeMaxDynamicSharedMemorySize,
                         DYN_SMEM);
    gram_f16<<<NTILES * NSPLIT, 192, DYN_SMEM>>>(out, nchunks, 0.5f / (float)N);
}